// round 6
// baseline (speedup 1.0000x reference)
#include <cuda_runtime.h>
#include <math_constants.h>
#include <cstdint>

#define POOL 7
#define NUM_ROIS 300
#define HH 50
#define WW 50
#define CC 512
#define NPIX (HH * WW)
#define NBINS (POOL * POOL)
#define V8_PER_BIN (CC / 8)               // 64 x 32B per bin
#define V8_PER_ROI (NBINS * V8_PER_BIN)   // 3136 x 32B per roi

// Scratch: channel-max per pixel (10 KB). __device__ global (no allocation).
__device__ float g_fmax[NPIX];

// K1: one warp per pixel, reduce 512 contiguous fp32 -> 1 fp32.
__global__ void fmax_kernel(const float* __restrict__ fm) {
    int gwarp = (blockIdx.x * blockDim.x + threadIdx.x) >> 5;
    int lane  = threadIdx.x & 31;
    if (gwarp < NPIX) {
        const float4* p = reinterpret_cast<const float4*>(fm + (size_t)gwarp * CC);
        float m = -CUDART_INF_F;
#pragma unroll
        for (int i = 0; i < 4; i++) {
            float4 v = p[lane + i * 32];
            m = fmaxf(m, fmaxf(fmaxf(v.x, v.y), fmaxf(v.z, v.w)));
        }
#pragma unroll
        for (int s = 16; s; s >>= 1)
            m = fmaxf(m, __shfl_xor_sync(0xffffffffu, m, s));
        if (lane == 0) g_fmax[gwarp] = m;
    }
    // PDL: signal dependent kernel once this CTA's writes are done.
    cudaTriggerProgrammaticLaunchCompletion();
}

// K2: one block per ROI; 256-bit broadcast stores.
__global__ void __launch_bounds__(256) roi_kernel(
    const float* __restrict__ rois, float* __restrict__ out) {
    __shared__ float s_fmax[NPIX];
    __shared__ float s_bin[NBINS];

    int roi = blockIdx.x;
    int tid = threadIdx.x;

    // Prologue overlaps K1 tail under PDL: roi scalars via constant path.
    const float inv = 1.0f / 16.0f;
    int x1 = (int)(rois[roi * 5 + 1] * inv);
    int y1 = (int)(rois[roi * 5 + 2] * inv);
    int x2 = (int)(rois[roi * 5 + 3] * inv);
    int y2 = (int)(rois[roi * 5 + 4] * inv);
    int rh = y2 - y1 + 1;
    int rw = x2 - x1 + 1;

    // Wait for K1's g_fmax to be globally visible.
    cudaGridDependencySynchronize();

    for (int i = tid; i < NPIX; i += 256)
        s_fmax[i] = g_fmax[i];
    __syncthreads();

    if (tid < NBINS) {
        int bi = tid / POOL;
        int bj = tid - bi * POOL;
        int hs = min(max(y1 + (bi * rh) / POOL, 0), HH);
        int he = min(max(y1 + ((bi + 1) * rh + POOL - 1) / POOL, 0), HH);
        int ws = min(max(x1 + (bj * rw) / POOL, 0), WW);
        int we = min(max(x1 + ((bj + 1) * rw + POOL - 1) / POOL, 0), WW);
        float m = -CUDART_INF_F;
        for (int r = hs; r < he; r++)
            for (int c = ws; c < we; c++)
                m = fmaxf(m, s_fmax[r * WW + c]);
        s_bin[tid] = m;
    }
    __syncthreads();

    // Broadcast stream: 3136 x 32B per ROI via st.global.v8.f32 (STG.256).
    float* base = out + (size_t)roi * (NBINS * CC);
#pragma unroll 4
    for (int i = tid; i < V8_PER_ROI; i += 256) {
        float v = s_bin[i >> 6];                 // i / V8_PER_BIN
        float* p = base + (size_t)i * 8;
        asm volatile(
            "st.global.v8.f32 [%0], {%1,%2,%3,%4,%5,%6,%7,%8};"
            :: "l"(p), "f"(v), "f"(v), "f"(v), "f"(v),
               "f"(v), "f"(v), "f"(v), "f"(v)
            : "memory");
    }
}

extern "C" void kernel_launch(void* const* d_in, const int* in_sizes, int n_in,
                              void* d_out, int out_size) {
    const float* rois = (const float*)d_in[0];
    const float* fm   = (const float*)d_in[1];
    if (in_sizes[0] != NUM_ROIS * 5) {
        const float* t = rois; rois = fm; fm = t;
    }
    float* out = (float*)d_out;

    int threads1 = 256;
    int blocks1  = (NPIX * 32 + threads1 - 1) / threads1;
    fmax_kernel<<<blocks1, threads1>>>(fm);

    // K2 with programmatic stream serialization (PDL).
    cudaLaunchAttribute attrs[1];
    attrs[0].id = cudaLaunchAttributeProgrammaticStreamSerialization;
    attrs[0].val.programmaticStreamSerializationAllowed = 1;

    cudaLaunchConfig_t cfg = {};
    cfg.gridDim  = dim3(NUM_ROIS, 1, 1);
    cfg.blockDim = dim3(256, 1, 1);
    cfg.dynamicSmemBytes = 0;
    cfg.stream   = 0;
    cfg.attrs    = attrs;
    cfg.numAttrs = 1;

    cudaLaunchKernelEx(&cfg, roi_kernel, rois, out);
}

// round 7
// speedup vs baseline: 1.0841x; 1.0841x over previous
#include <cuda_runtime.h>
#include <math_constants.h>
#include <cstdint>

#define POOL 7
#define NUM_ROIS 300
#define HH 50
#define WW 50
#define CC 512
#define NPIX (HH * WW)
#define NBINS (POOL * POOL)
#define TOTAL_BINS (NUM_ROIS * NBINS)     // 14700
#define BINS_PER_BLOCK 4
#define GRID2 (TOTAL_BINS / BINS_PER_BLOCK) // 3675
#define V4_PER_BIN (CC / 4)               // 128 float4 per bin
#define V4_PER_BLOCK (BINS_PER_BLOCK * V4_PER_BIN) // 512

// Scratch: channel-max per pixel (10 KB). __device__ global (no allocation).
__device__ float g_fmax[NPIX];

// K1: one warp per pixel, reduce 512 contiguous fp32 -> 1 fp32.
__global__ void fmax_kernel(const float* __restrict__ fm) {
    int gwarp = (blockIdx.x * blockDim.x + threadIdx.x) >> 5;
    int lane  = threadIdx.x & 31;
    if (gwarp >= NPIX) return;
    const float4* p = reinterpret_cast<const float4*>(fm + (size_t)gwarp * CC);
    float m = -CUDART_INF_F;
#pragma unroll
    for (int i = 0; i < 4; i++) {
        float4 v = p[lane + i * 32];
        m = fmaxf(m, fmaxf(fmaxf(v.x, v.y), fmaxf(v.z, v.w)));
    }
#pragma unroll
    for (int s = 16; s; s >>= 1)
        m = fmaxf(m, __shfl_xor_sync(0xffffffffu, m, s));
    if (lane == 0) g_fmax[gwarp] = m;
}

// K2: 4 bins per block (one warp per bin), then stream 8KB of broadcast
// output. Store issue cost is spread evenly across all SMSPs on the chip.
__global__ void __launch_bounds__(128) bin_stream_kernel(
    const float* __restrict__ rois, float* __restrict__ out) {
    __shared__ float s_bin[BINS_PER_BLOCK];

    int tid  = threadIdx.x;
    int wid  = tid >> 5;
    int lane = tid & 31;

    // ---- Warp w computes bin (4*bid + w) ----
    int g   = blockIdx.x * BINS_PER_BLOCK + wid;   // global bin id
    int roi = g / NBINS;
    int bin = g - roi * NBINS;
    int bi  = bin / POOL;
    int bj  = bin - bi * POOL;

    const float inv = 1.0f / 16.0f;
    int x1 = (int)(rois[roi * 5 + 1] * inv);       // uniform across warp (L1-hot)
    int y1 = (int)(rois[roi * 5 + 2] * inv);
    int x2 = (int)(rois[roi * 5 + 3] * inv);
    int y2 = (int)(rois[roi * 5 + 4] * inv);
    int rh = y2 - y1 + 1;
    int rw = x2 - x1 + 1;

    int hs = min(max(y1 + (bi * rh) / POOL, 0), HH);
    int he = min(max(y1 + ((bi + 1) * rh + POOL - 1) / POOL, 0), HH);
    int ws = min(max(x1 + (bj * rw) / POOL, 0), WW);
    int we = min(max(x1 + ((bj + 1) * rw + POOL - 1) / POOL, 0), WW);

    int nh = he - hs;
    int nw = we - ws;
    int n  = (nh > 0 && nw > 0) ? nh * nw : 0;     // <= 64 cells

    float m = -CUDART_INF_F;
    for (int idx = lane; idx < n; idx += 32) {     // <= 2 iters (L2-hot loads)
        int r = idx / nw;
        int c = idx - r * nw;
        m = fmaxf(m, g_fmax[(hs + r) * WW + (ws + c)]);
    }
#pragma unroll
    for (int s = 16; s; s >>= 1)
        m = fmaxf(m, __shfl_xor_sync(0xffffffffu, m, s));
    if (lane == 0) s_bin[wid] = m;
    __syncthreads();

    // ---- Stream 512 float4 (8KB): 4 STG.128 per thread ----
    float4* out4 = reinterpret_cast<float4*>(out) + (size_t)blockIdx.x * V4_PER_BLOCK;
#pragma unroll
    for (int k = 0; k < 4; k++) {
        int i = tid + k * 128;                     // i >> 7 == k: bin k
        float v = s_bin[k];
        out4[i] = make_float4(v, v, v, v);
    }
}

extern "C" void kernel_launch(void* const* d_in, const int* in_sizes, int n_in,
                              void* d_out, int out_size) {
    const float* rois = (const float*)d_in[0];
    const float* fm   = (const float*)d_in[1];
    if (in_sizes[0] != NUM_ROIS * 5) {
        const float* t = rois; rois = fm; fm = t;
    }
    float* out = (float*)d_out;

    int threads1 = 256;
    int blocks1  = (NPIX * 32 + threads1 - 1) / threads1;
    fmax_kernel<<<blocks1, threads1>>>(fm);

    bin_stream_kernel<<<GRID2, 128>>>(rois, out);
}